// round 5
// baseline (speedup 1.0000x reference)
#include <cuda_runtime.h>
#include <cuda_fp16.h>
#include <math.h>
#include <stdint.h>

#define NB 8192
#define NH 2048
#define NR 64

// fp32 scratch
__device__ float g_q[NB * NR];
__device__ float g_k[NB * NR];
__device__ float g_v[NB * NR];
// fp16 scratch
__device__ __half g_hp16[NB * NH];     // h_prev fp16
__device__ __half g_xt16[NB * NH];     // x_t fp16
__device__ __half g_ww16[NH * NH];     // W_w fp16
__device__ __half g_uw16[NH * NH];     // U_w fp16
__device__ __half g_wq16[NR * NH];
__device__ __half g_wk16[NR * NH];
__device__ __half g_wv16[NR * NH];
__device__ __half g_wo16[NH * NR];
__device__ __half g_hth[NB * NH];      // h_t fp16 (k1 epilogue -> k2)
__device__ __half g_rv16[NB * NR];     // routed_v fp16 (k3 -> k4)

// ---------------------------------------------------------------------------
// helpers (sm_80-compatible; NO 'a'-suffix features)
// ---------------------------------------------------------------------------
__device__ __forceinline__ uint32_t smem_u32(const void* p) {
    uint32_t a;
    asm("{ .reg .u64 t; cvta.to.shared.u64 t, %1; cvt.u32.u64 %0, t; }"
        : "=r"(a) : "l"(p));
    return a;
}
#define LDMATRIX_X4(r, addr)                                                    \
    asm volatile("ldmatrix.sync.aligned.m8n8.x4.shared.b16 {%0,%1,%2,%3}, [%4];"\
        : "=r"((r)[0]), "=r"((r)[1]), "=r"((r)[2]), "=r"((r)[3]) : "r"(addr))

__device__ __forceinline__ void mma_f16(float c[4], const uint32_t a[4],
                                        uint32_t b0, uint32_t b1) {
    asm volatile(
        "mma.sync.aligned.m16n8k16.row.col.f32.f16.f16.f32 "
        "{%0,%1,%2,%3}, {%4,%5,%6,%7}, {%8,%9}, {%0,%1,%2,%3};"
        : "+f"(c[0]), "+f"(c[1]), "+f"(c[2]), "+f"(c[3])
        : "r"(a[0]), "r"(a[1]), "r"(a[2]), "r"(a[3]), "r"(b0), "r"(b1));
}

#define CP_ASYNC16(saddr, gptr)                                                \
    asm volatile("cp.async.cg.shared.global [%0], [%1], 16;"                   \
        :: "r"(saddr), "l"(gptr) : "memory")
#define CP_COMMIT() asm volatile("cp.async.commit_group;" ::: "memory")
#define CP_WAIT2()  asm volatile("cp.async.wait_group 2;" ::: "memory")
#define CP_WAIT1()  asm volatile("cp.async.wait_group 1;" ::: "memory")
#define CP_WAIT0()  asm volatile("cp.async.wait_group 0;" ::: "memory")

// ---------------------------------------------------------------------------
// pre-pass: fp32 -> fp16 (RN)
// ---------------------------------------------------------------------------
__global__ void cvt16(const float* __restrict__ src, __half* __restrict__ dst,
                      int n4)
{
    const int i = blockIdx.x * blockDim.x + threadIdx.x;
    if (i < n4) {
        float4 v = ((const float4*)src)[i];
        ((__half2*)dst)[2 * i]     = __floats2half2_rn(v.x, v.y);
        ((__half2*)dst)[2 * i + 1] = __floats2half2_rn(v.z, v.w);
    }
}

// ---------------------------------------------------------------------------
// Kernel 1 (fp16 mma, frag double-buffered): h_t = (1-sigmoid(alpha))*h_prev
//                            + tanh(h_prev@W_w^T + x_t@U_w^T + U_b)
// M=8192 (batch), N=2048 (hidden), K=4096 (two segments).
// BM=128, BN=256, BK=64, 512 thr (16 warps 2x8), warp tile 64x32.
// 4-stage cp.async (wait_group 2); ldmatrix fragments register-double-buffered
// so MMA issue never stalls on LDSM latency.
// ---------------------------------------------------------------------------
#define K1_STAGE 49152                         // A 16KB + B 32KB
#define K1_NSTAGE 4
#define K1_SMEM (K1_NSTAGE * K1_STAGE)         // 192KB

__global__ __launch_bounds__(512, 1)
void k1_liquid_f16(const float* __restrict__ h_prev,
                   const float* __restrict__ U_b,
                   const float* __restrict__ alpha_raw,
                   float* __restrict__ h_t)
{
    extern __shared__ char sm[];
    const uint32_t sbase = smem_u32(sm);

    const int tid  = threadIdx.x;
    const int wid  = tid >> 5;
    const int lane = tid & 31;
    const int warp_m = wid & 1;
    const int warp_n = wid >> 1;
    const int m0 = blockIdx.y * 128;
    const int n0 = blockIdx.x * 256;

    auto load_stage = [&](int kt, int s) {
        const __half* Asrc = (kt < 32) ? g_hp16 : g_xt16;
        const __half* Bsrc = (kt < 32) ? g_ww16 : g_uw16;
        const int k0 = (kt & 31) << 6;
        const uint32_t sa = sbase + s * K1_STAGE;
        const uint32_t sb = sa + 16384;
#pragma unroll
        for (int i = 0; i < 2; ++i) {            // A: 1024 x 16B / 512 thr
            const int id = tid + 512 * i;
            const int row = id >> 3, c = id & 7;
            CP_ASYNC16(sa + row * 128 + ((c ^ (row & 7)) << 4),
                       Asrc + (size_t)(m0 + row) * NH + k0 + c * 8);
        }
#pragma unroll
        for (int i = 0; i < 4; ++i) {            // B: 2048 x 16B / 512 thr
            const int id = tid + 512 * i;
            const int row = id >> 3, c = id & 7;
            CP_ASYNC16(sb + row * 128 + ((c ^ (row & 7)) << 4),
                       Bsrc + (size_t)(n0 + row) * NH + k0 + c * 8);
        }
    };

    float acc[4][4][4];
#pragma unroll
    for (int a = 0; a < 4; ++a)
#pragma unroll
        for (int b = 0; b < 4; ++b)
#pragma unroll
            for (int d = 0; d < 4; ++d) acc[a][b][d] = 0.f;

    const int rl16 = lane & 15;         // row within 16-row frag
    const int ksel = lane >> 4;         // 16B k-chunk select (0/1)
    uint32_t aOff[4]; int aSwz[4];
    uint32_t bOff[2]; int bSwz[2];
#pragma unroll
    for (int mt = 0; mt < 4; ++mt) {
        const int r = warp_m * 64 + mt * 16 + rl16;
        aOff[mt] = r * 128; aSwz[mt] = r & 7;
    }
#pragma unroll
    for (int p = 0; p < 2; ++p) {
        const int r = warp_n * 32 + p * 16 + rl16;
        bOff[p] = 16384 + r * 128; bSwz[p] = r & 7;
    }

    // prologue: stages 0..2 in flight
    load_stage(0, 0); CP_COMMIT();
    load_stage(1, 1); CP_COMMIT();
    load_stage(2, 2); CP_COMMIT();

    uint32_t fa[2][4][4], fb[2][2][4];

    CP_WAIT2();                 // stage 0 resident
    __syncthreads();
    {   // frags for (kt=0, ks=0) -> buffer 0
        const int chunk = ksel;
#pragma unroll
        for (int mt = 0; mt < 4; ++mt)
            LDMATRIX_X4(fa[0][mt], sbase + aOff[mt] + ((chunk ^ aSwz[mt]) << 4));
#pragma unroll
        for (int p = 0; p < 2; ++p)
            LDMATRIX_X4(fb[0][p], sbase + bOff[p] + ((chunk ^ bSwz[p]) << 4));
    }

    for (int kt = 0; kt < 64; ++kt) {
        const uint32_t stage  = sbase + (kt % K1_NSTAGE) * K1_STAGE;
        const uint32_t nstage = sbase + ((kt + 1) % K1_NSTAGE) * K1_STAGE;
#pragma unroll
        for (int ks = 0; ks < 4; ++ks) {
            const int cur = ks & 1, nxt = cur ^ 1;
            if (ks == 0) {                       // feed stage kt+3
                if (kt + 3 < 64) load_stage(kt + 3, (kt + 3) % K1_NSTAGE);
                CP_COMMIT();
            }
            if (ks < 3) {                        // frags for ks+1 (this stage)
                const int chunk = (ks + 1) * 2 + ksel;
#pragma unroll
                for (int mt = 0; mt < 4; ++mt)
                    LDMATRIX_X4(fa[nxt][mt],
                                stage + aOff[mt] + ((chunk ^ aSwz[mt]) << 4));
#pragma unroll
                for (int p = 0; p < 2; ++p)
                    LDMATRIX_X4(fb[nxt][p],
                                stage + bOff[p] + ((chunk ^ bSwz[p]) << 4));
            }
            if (ks == 2) {                       // stage kt+1 ready; kt reads done
                CP_WAIT2();
                __syncthreads();
            }
            if (ks == 3 && kt + 1 < 64) {        // frags for (kt+1, ks=0)
                const int chunk = ksel;
#pragma unroll
                for (int mt = 0; mt < 4; ++mt)
                    LDMATRIX_X4(fa[nxt][mt],
                                nstage + aOff[mt] + ((chunk ^ aSwz[mt]) << 4));
#pragma unroll
                for (int p = 0; p < 2; ++p)
                    LDMATRIX_X4(fb[nxt][p],
                                nstage + bOff[p] + ((chunk ^ bSwz[p]) << 4));
            }
#pragma unroll
            for (int mt = 0; mt < 4; ++mt)
#pragma unroll
                for (int nt = 0; nt < 4; ++nt)
                    mma_f16(acc[mt][nt], fa[cur][mt],
                            fb[cur][nt >> 1][nt & 1],
                            fb[cur][nt >> 1][2 + (nt & 1)]);
        }
    }

    // epilogue: fp32 gating + tanh; also emit fp16 h_t copy for k2
    const int g = lane >> 2, tig = lane & 3;
    const int mBase = m0 + warp_m * 64;
    const int nBase = n0 + warp_n * 32;
#pragma unroll
    for (int nt = 0; nt < 4; ++nt) {
        const int n = nBase + nt * 8 + tig * 2;
        const float om0 = 1.f / (1.f + __expf(alpha_raw[n]));
        const float om1 = 1.f / (1.f + __expf(alpha_raw[n + 1]));
        const float bi0 = U_b[n], bi1 = U_b[n + 1];
#pragma unroll
        for (int mt = 0; mt < 4; ++mt) {
            int m = mBase + mt * 16 + g;
            float2 hp = *(const float2*)(h_prev + (size_t)m * NH + n);
            float2 o;
            o.x = om0 * hp.x + tanhf(acc[mt][nt][0] + bi0);
            o.y = om1 * hp.y + tanhf(acc[mt][nt][1] + bi1);
            *(float2*)(h_t + (size_t)m * NH + n) = o;
            *(__half2*)(g_hth + (size_t)m * NH + n) = __floats2half2_rn(o.x, o.y);
            m += 8;
            hp = *(const float2*)(h_prev + (size_t)m * NH + n);
            o.x = om0 * hp.x + tanhf(acc[mt][nt][2] + bi0);
            o.y = om1 * hp.y + tanhf(acc[mt][nt][3] + bi1);
            *(float2*)(h_t + (size_t)m * NH + n) = o;
            *(__half2*)(g_hth + (size_t)m * NH + n) = __floats2half2_rn(o.x, o.y);
        }
    }
}

// ---------------------------------------------------------------------------
// Kernel 2 (fp16 mma): q/k/v = h_t @ W{Q,K,V}^T  (M=8192, N=64, K=2048)
// BM=128, BN=64, BK=64, 256 thr (8 warps 4x2), warp tile 32x32, 3 stages.
// ---------------------------------------------------------------------------
#define K2_STAGE 24576                         // A 16KB + B 8KB
#define K2_SMEM (3 * K2_STAGE)

__global__ __launch_bounds__(256, 1)
void k2_qkv_f16()
{
    extern __shared__ char sm[];
    const uint32_t sbase = smem_u32(sm);

    const int tid  = threadIdx.x;
    const int wid  = tid >> 5;
    const int lane = tid & 31;
    const int warp_m = wid & 3;
    const int warp_n = wid >> 2;
    const int m0 = blockIdx.x * 128;
    const int z  = blockIdx.z;
    const __half* Bsrc = (z == 0) ? g_wq16 : (z == 1) ? g_wk16 : g_wv16;
    float* out         = (z == 0) ? g_q : (z == 1) ? g_k : g_v;

    auto load_stage = [&](int kt, int s) {
        const int k0 = kt << 6;
        const uint32_t sa = sbase + s * K2_STAGE;
        const uint32_t sb = sa + 16384;
#pragma unroll
        for (int i = 0; i < 4; ++i) {            // A: 1024 x 16B / 256 thr
            const int id = tid + 256 * i;
            const int row = id >> 3, c = id & 7;
            CP_ASYNC16(sa + row * 128 + ((c ^ (row & 7)) << 4),
                       g_hth + (size_t)(m0 + row) * NH + k0 + c * 8);
        }
#pragma unroll
        for (int i = 0; i < 2; ++i) {            // B: 512 x 16B / 256 thr
            const int id = tid + 256 * i;
            const int row = id >> 3, c = id & 7;
            CP_ASYNC16(sb + row * 128 + ((c ^ (row & 7)) << 4),
                       Bsrc + (size_t)row * NH + k0 + c * 8);
        }
    };

    float acc[2][4][4];
#pragma unroll
    for (int a = 0; a < 2; ++a)
#pragma unroll
        for (int b = 0; b < 4; ++b)
#pragma unroll
            for (int d = 0; d < 4; ++d) acc[a][b][d] = 0.f;

    load_stage(0, 0); CP_COMMIT();
    load_stage(1, 1); CP_COMMIT();

    const int rl16 = lane & 15;
    const int ksel = lane >> 4;
    uint32_t aOff[2]; int aSwz[2];
    uint32_t bOff[2]; int bSwz[2];
#pragma unroll
    for (int mt = 0; mt < 2; ++mt) {
        const int r = warp_m * 32 + mt * 16 + rl16;
        aOff[mt] = r * 128; aSwz[mt] = r & 7;
    }
#pragma unroll
    for (int p = 0; p < 2; ++p) {
        const int r = warp_n * 32 + p * 16 + rl16;
        bOff[p] = 16384 + r * 128; bSwz[p] = r & 7;
    }

    for (int kt = 0; kt < 32; ++kt) {
        const int s = kt % 3;
        CP_WAIT1();
        __syncthreads();
        if (kt + 2 < 32) load_stage(kt + 2, (kt + 2) % 3);
        CP_COMMIT();

        const uint32_t stage = sbase + s * K2_STAGE;
#pragma unroll
        for (int ks = 0; ks < 4; ++ks) {
            const int chunk = ks * 2 + ksel;
            uint32_t a[2][4], b[2][4];
#pragma unroll
            for (int mt = 0; mt < 2; ++mt)
                LDMATRIX_X4(a[mt], stage + aOff[mt] + ((chunk ^ aSwz[mt]) << 4));
#pragma unroll
            for (int p = 0; p < 2; ++p)
                LDMATRIX_X4(b[p], stage + bOff[p] + ((chunk ^ bSwz[p]) << 4));
#pragma unroll
            for (int mt = 0; mt < 2; ++mt)
#pragma unroll
                for (int nt = 0; nt < 4; ++nt)
                    mma_f16(acc[mt][nt], a[mt],
                            b[nt >> 1][nt & 1], b[nt >> 1][2 + (nt & 1)]);
        }
    }

    const int g = lane >> 2, tig = lane & 3;
    const int mBase = m0 + warp_m * 32;
    const int nBase = warp_n * 32;
#pragma unroll
    for (int nt = 0; nt < 4; ++nt) {
        const int n = nBase + nt * 8 + tig * 2;
#pragma unroll
        for (int mt = 0; mt < 2; ++mt) {
            int m = mBase + mt * 16 + g;
            *(float2*)(out + (size_t)m * NR + n) =
                make_float2(acc[mt][nt][0], acc[mt][nt][1]);
            m += 8;
            *(float2*)(out + (size_t)m * NR + n) =
                make_float2(acc[mt][nt][2], acc[mt][nt][3]);
        }
    }
}

// ---------------------------------------------------------------------------
// Kernel 3: per-row outer-product softmax routing.
// ---------------------------------------------------------------------------
__global__ __launch_bounds__(256)
void k3_attn()
{
    const int warp = (blockIdx.x * blockDim.x + threadIdx.x) >> 5;
    const int lane = threadIdx.x & 31;
    if (warp >= NB) return;

    const float* q = g_q + (size_t)warp * NR;
    const float* k = g_k + (size_t)warp * NR;
    const float* v = g_v + (size_t)warp * NR;
    const unsigned full = 0xffffffffu;

    const float q0 = q[lane], q1 = q[lane + 32];
    const float k0 = k[lane], k1 = k[lane + 32];
    const float v0 = v[lane], v1 = v[lane + 32];

    float kmx = fmaxf(k0, k1), kmn = fminf(k0, k1);
#pragma unroll
    for (int o = 16; o; o >>= 1) {
        kmx = fmaxf(kmx, __shfl_xor_sync(full, kmx, o));
        kmn = fminf(kmn, __shfl_xor_sync(full, kmn, o));
    }
    const float m0 = 0.125f * q0 * ((q0 >= 0.f) ? kmx : kmn);
    const float m1 = 0.125f * q1 * ((q1 >= 0.f) ? kmx : kmn);

    float se0 = 0.f, sd0 = 0.f, se1 = 0.f, sd1 = 0.f;
#pragma unroll 8
    for (int j = 0; j < 32; ++j) {
        const float kj = __shfl_sync(full, k0, j);
        const float vj = __shfl_sync(full, v0, j);
        const float e0 = __expf(fmaf(0.125f * q0, kj, -m0));
        const float e1 = __expf(fmaf(0.125f * q1, kj, -m1));
        se0 += e0; sd0 = fmaf(e0, vj, sd0);
        se1 += e1; sd1 = fmaf(e1, vj, sd1);
    }
#pragma unroll 8
    for (int j = 0; j < 32; ++j) {
        const float kj = __shfl_sync(full, k1, j);
        const float vj = __shfl_sync(full, v1, j);
        const float e0 = __expf(fmaf(0.125f * q0, kj, -m0));
        const float e1 = __expf(fmaf(0.125f * q1, kj, -m1));
        se0 += e0; sd0 = fmaf(e0, vj, sd0);
        se1 += e1; sd1 = fmaf(e1, vj, sd1);
    }

    g_rv16[(size_t)warp * NR + lane]      = __float2half(sd0 / se0);
    g_rv16[(size_t)warp * NR + 32 + lane] = __float2half(sd1 / se1);
}

// ---------------------------------------------------------------------------
// Kernel 4 (fp16 mma, single K-shot): y = gamma*(rv @ WO^T) + x_t
// ---------------------------------------------------------------------------
__global__ __launch_bounds__(512, 1)
void k4_out_f16(const float* __restrict__ x_t,
                const float* __restrict__ gamma,
                float* __restrict__ y)
{
    __shared__ __align__(16) char sm4[49152];
    const uint32_t sbase = smem_u32(sm4);

    const int tid  = threadIdx.x;
    const int wid  = tid >> 5;
    const int lane = tid & 31;
    const int warp_m = wid & 1;
    const int warp_n = wid >> 1;
    const int m0 = blockIdx.y * 128;
    const int n0 = blockIdx.x * 256;

#pragma unroll
    for (int i = 0; i < 2; ++i) {
        const int id = tid + 512 * i;
        const int row = id >> 3, c = id & 7;
        CP_ASYNC16(sbase + row * 128 + ((c ^ (row & 7)) << 4),
                   g_rv16 + (size_t)(m0 + row) * NR + c * 8);
    }
#pragma unroll
    for (int i = 0; i < 4; ++i) {
        const int id = tid + 512 * i;
        const int row = id >> 3, c = id & 7;
        CP_ASYNC16(sbase + 16384 + row * 128 + ((c ^ (row & 7)) << 4),
                   g_wo16 + (size_t)(n0 + row) * NR + c * 8);
    }
    CP_COMMIT(); CP_WAIT0();
    __syncthreads();

    const int rl16 = lane & 15;
    const int ksel = lane >> 4;
    float acc[4][4][4];
#pragma unroll
    for (int a = 0; a < 4; ++a)
#pragma unroll
        for (int b = 0; b < 4; ++b)
#pragma unroll
            for (int d = 0; d < 4; ++d) acc[a][b][d] = 0.f;

#pragma unroll
    for (int ks = 0; ks < 4; ++ks) {
        const int chunk = ks * 2 + ksel;
        uint32_t a[4][4], b[2][4];
#pragma unroll
        for (int mt = 0; mt < 4; ++mt) {
            const int r = warp_m * 64 + mt * 16 + rl16;
            LDMATRIX_X4(a[mt], sbase + r * 128 + ((chunk ^ (r & 7)) << 4));
        }
#pragma unroll
        for (int p = 0; p < 2; ++p) {
            const int r = warp_n * 32 + p * 16 + rl16;
            LDMATRIX_X4(b[p], sbase + 16384 + r * 128 + ((chunk ^ (r & 7)) << 4));
        }
#pragma unroll
        for (int mt = 0; mt < 4; ++mt)
#pragma unroll
            for (int nt = 0; nt < 4; ++nt)
                mma_f16(acc[mt][nt], a[mt],
                        b[nt >> 1][nt & 1], b[nt >> 1][2 + (nt & 1)]);
    }

    const float gm = gamma[0];
    const int g = lane >> 2, tig = lane & 3;
    const int mBase = m0 + warp_m * 64;
    const int nBase = n0 + warp_n * 32;
#pragma unroll
    for (int nt = 0; nt < 4; ++nt) {
        const int n = nBase + nt * 8 + tig * 2;
#pragma unroll
        for (int mt = 0; mt < 4; ++mt) {
            int m = mBase + mt * 16 + g;
            float2 xv = *(const float2*)(x_t + (size_t)m * NH + n);
            float2 o;
            o.x = fmaf(gm, acc[mt][nt][0], xv.x);
            o.y = fmaf(gm, acc[mt][nt][1], xv.y);
            *(float2*)(y + (size_t)m * NH + n) = o;
            m += 8;
            xv = *(const float2*)(x_t + (size_t)m * NH + n);
            o.x = fmaf(gm, acc[mt][nt][2], xv.x);
            o.y = fmaf(gm, acc[mt][nt][3], xv.y);
            *(float2*)(y + (size_t)m * NH + n) = o;
        }
    }
}

// ---------------------------------------------------------------------------
extern "C" void kernel_launch(void* const* d_in, const int* in_sizes, int n_in,
                              void* d_out, int out_size)
{
    const float* h_prev    = (const float*)d_in[0];
    const float* x_t       = (const float*)d_in[1];
    const float* U_w       = (const float*)d_in[2];
    const float* U_b       = (const float*)d_in[3];
    const float* W_w       = (const float*)d_in[4];
    const float* alpha_raw = (const float*)d_in[5];
    const float* WQ        = (const float*)d_in[6];
    const float* WK        = (const float*)d_in[7];
    const float* WV        = (const float*)d_in[8];
    const float* WO        = (const float*)d_in[9];
    const float* gamma     = (const float*)d_in[10];

    float* h_t = (float*)d_out;
    float* y_t = h_t + (size_t)NB * NH;

    cudaFuncSetAttribute(k1_liquid_f16,
                         cudaFuncAttributeMaxDynamicSharedMemorySize, K1_SMEM);
    cudaFuncSetAttribute(k2_qkv_f16,
                         cudaFuncAttributeMaxDynamicSharedMemorySize, K2_SMEM);

    __half *d_hp16, *d_xt16, *d_ww16, *d_uw16, *d_wq16, *d_wk16, *d_wv16, *d_wo16;
    cudaGetSymbolAddress((void**)&d_hp16, g_hp16);
    cudaGetSymbolAddress((void**)&d_xt16, g_xt16);
    cudaGetSymbolAddress((void**)&d_ww16, g_ww16);
    cudaGetSymbolAddress((void**)&d_uw16, g_uw16);
    cudaGetSymbolAddress((void**)&d_wq16, g_wq16);
    cudaGetSymbolAddress((void**)&d_wk16, g_wk16);
    cudaGetSymbolAddress((void**)&d_wv16, g_wv16);
    cudaGetSymbolAddress((void**)&d_wo16, g_wo16);

    const int big4 = NB * NH / 4;
    const int ww4  = NH * NH / 4;
    const int w64  = NR * NH / 4;
    cvt16<<<(big4 + 255) / 256, 256>>>(h_prev, d_hp16, big4);
    cvt16<<<(big4 + 255) / 256, 256>>>(x_t,    d_xt16, big4);
    cvt16<<<(ww4 + 255) / 256, 256>>>(W_w,     d_ww16, ww4);
    cvt16<<<(ww4 + 255) / 256, 256>>>(U_w,     d_uw16, ww4);
    cvt16<<<(w64 + 255) / 256, 256>>>(WQ,      d_wq16, w64);
    cvt16<<<(w64 + 255) / 256, 256>>>(WK,      d_wk16, w64);
    cvt16<<<(w64 + 255) / 256, 256>>>(WV,      d_wv16, w64);
    cvt16<<<(w64 + 255) / 256, 256>>>(WO,      d_wo16, w64);

    dim3 g1(NH / 256, NB / 128);                      // (8, 64)
    k1_liquid_f16<<<g1, 512, K1_SMEM>>>(h_prev, U_b, alpha_raw, h_t);

    dim3 g2(NB / 128, 1, 3);                          // (64, 1, 3)
    k2_qkv_f16<<<g2, 256, K2_SMEM>>>();

    k3_attn<<<NB / 8, 256>>>();

    dim3 g4(NH / 256, NB / 128);                      // (8, 64)
    k4_out_f16<<<g4, 512>>>(x_t, gamma, y_t);
}

// round 6
// speedup vs baseline: 1.2193x; 1.2193x over previous
#include <cuda_runtime.h>
#include <cuda_fp16.h>
#include <math.h>
#include <stdint.h>

#define NB 8192
#define NH 2048
#define NR 64

// fp32 scratch
__device__ float g_q[NB * NR];
__device__ float g_k[NB * NR];
__device__ float g_v[NB * NR];
// fp16 scratch
__device__ __half g_hp16[NB * NH];
__device__ __half g_xt16[NB * NH];
__device__ __half g_ww16[NH * NH];
__device__ __half g_uw16[NH * NH];
__device__ __half g_wq16[NR * NH];
__device__ __half g_wk16[NR * NH];
__device__ __half g_wv16[NR * NH];
__device__ __half g_wo16[NH * NR];
__device__ __half g_hth[NB * NH];      // h_t fp16 (k1 -> k2)
__device__ __half g_rv16[NB * NR];     // routed_v fp16 (k3 -> k4)

// ---------------------------------------------------------------------------
// helpers (sm_80-compatible; NO 'a'-suffix features)
// ---------------------------------------------------------------------------
__device__ __forceinline__ uint32_t smem_u32(const void* p) {
    uint32_t a;
    asm("{ .reg .u64 t; cvta.to.shared.u64 t, %1; cvt.u32.u64 %0, t; }"
        : "=r"(a) : "l"(p));
    return a;
}
#define LDMATRIX_X4(r, addr)                                                    \
    asm volatile("ldmatrix.sync.aligned.m8n8.x4.shared.b16 {%0,%1,%2,%3}, [%4];"\
        : "=r"((r)[0]), "=r"((r)[1]), "=r"((r)[2]), "=r"((r)[3]) : "r"(addr))

__device__ __forceinline__ void mma_f16(float c[4], const uint32_t a[4],
                                        uint32_t b0, uint32_t b1) {
    asm volatile(
        "mma.sync.aligned.m16n8k16.row.col.f32.f16.f16.f32 "
        "{%0,%1,%2,%3}, {%4,%5,%6,%7}, {%8,%9}, {%0,%1,%2,%3};"
        : "+f"(c[0]), "+f"(c[1]), "+f"(c[2]), "+f"(c[3])
        : "r"(a[0]), "r"(a[1]), "r"(a[2]), "r"(a[3]), "r"(b0), "r"(b1));
}

#define CP_ASYNC16(saddr, gptr)                                                \
    asm volatile("cp.async.cg.shared.global [%0], [%1], 16;"                   \
        :: "r"(saddr), "l"(gptr) : "memory")
#define CP_COMMIT() asm volatile("cp.async.commit_group;" ::: "memory")
#define CP_WAIT1()  asm volatile("cp.async.wait_group 1;" ::: "memory")
#define CP_WAIT0()  asm volatile("cp.async.wait_group 0;" ::: "memory")

// ---------------------------------------------------------------------------
// fused pre-pass: all fp32 -> fp16 conversions in ONE kernel
// segments (float4 units): hp 4194304 | xt 4194304 | ww 1048576 | uw 1048576 |
//                          wq 32768 | wk 32768 | wv 32768 | wo 32768
// total = 10616832 float4  -> 41472 blocks x 256
// ---------------------------------------------------------------------------
#define CVT_TOTAL4 10616832
__global__ __launch_bounds__(256)
void cvt_all(const float* __restrict__ hp, const float* __restrict__ xt,
             const float* __restrict__ ww, const float* __restrict__ uw,
             const float* __restrict__ wq, const float* __restrict__ wk,
             const float* __restrict__ wv, const float* __restrict__ wo)
{
    const int i = blockIdx.x * 256 + threadIdx.x;
    if (i >= CVT_TOTAL4) return;
    const float* src; __half* dst; int off;
    if (i < 4194304)        { src = hp; dst = g_hp16; off = i; }
    else if (i < 8388608)   { src = xt; dst = g_xt16; off = i - 4194304; }
    else if (i < 9437184)   { src = ww; dst = g_ww16; off = i - 8388608; }
    else if (i < 10485760)  { src = uw; dst = g_uw16; off = i - 9437184; }
    else if (i < 10518528)  { src = wq; dst = g_wq16; off = i - 10485760; }
    else if (i < 10551296)  { src = wk; dst = g_wk16; off = i - 10518528; }
    else if (i < 10584064)  { src = wv; dst = g_wv16; off = i - 10551296; }
    else                    { src = wo; dst = g_wo16; off = i - 10584064; }
    float4 v = ((const float4*)src)[off];
    ((__half2*)dst)[2 * off]     = __floats2half2_rn(v.x, v.y);
    ((__half2*)dst)[2 * off + 1] = __floats2half2_rn(v.z, v.w);
}

// ---------------------------------------------------------------------------
// Kernel 1 (fp16 mma): h_t = (1-sigmoid(alpha))*h_prev
//                            + tanh(h_prev@W_w^T + x_t@U_w^T + U_b)
// M=8192, N=2048, K=4096 (two segments).
// BM=128, BN=128, BK=64, 256 thr (8 warps 2x4), warp tile 64x32.
// 3-stage cp.async (32KB/stage, 96KB total) -> occupancy 2.
// 1024 CTAs => ~1% wave-quantization tail (vs 13.5% at 512 CTAs occ1).
// ---------------------------------------------------------------------------
#define K1_STAGE 32768                          // A 16KB + B 16KB
#define K1_SMEM (3 * K1_STAGE)                  // 96KB

__global__ __launch_bounds__(256, 2)
void k1_liquid_f16(const float* __restrict__ h_prev,
                   const float* __restrict__ U_b,
                   const float* __restrict__ alpha_raw,
                   float* __restrict__ h_t)
{
    extern __shared__ char sm[];
    const uint32_t sbase = smem_u32(sm);

    const int tid  = threadIdx.x;
    const int wid  = tid >> 5;
    const int lane = tid & 31;
    const int warp_m = wid & 1;       // 2 warps over M=128 (64 each)
    const int warp_n = wid >> 1;      // 4 warps over N=128 (32 each)
    const int m0 = blockIdx.y * 128;
    const int n0 = blockIdx.x * 128;

    auto load_stage = [&](int kt, int s) {
        const __half* Asrc = (kt < 32) ? g_hp16 : g_xt16;
        const __half* Bsrc = (kt < 32) ? g_ww16 : g_uw16;
        const int k0 = (kt & 31) << 6;
        const uint32_t sa = sbase + s * K1_STAGE;
        const uint32_t sb = sa + 16384;
#pragma unroll
        for (int i = 0; i < 4; ++i) {            // A: 1024 x 16B / 256 thr
            const int id = tid + 256 * i;
            const int row = id >> 3, c = id & 7;
            CP_ASYNC16(sa + row * 128 + ((c ^ (row & 7)) << 4),
                       Asrc + (size_t)(m0 + row) * NH + k0 + c * 8);
        }
#pragma unroll
        for (int i = 0; i < 4; ++i) {            // B: 1024 x 16B / 256 thr
            const int id = tid + 256 * i;
            const int row = id >> 3, c = id & 7;
            CP_ASYNC16(sb + row * 128 + ((c ^ (row & 7)) << 4),
                       Bsrc + (size_t)(n0 + row) * NH + k0 + c * 8);
        }
    };

    float acc[4][4][4];
#pragma unroll
    for (int a = 0; a < 4; ++a)
#pragma unroll
        for (int b = 0; b < 4; ++b)
#pragma unroll
            for (int d = 0; d < 4; ++d) acc[a][b][d] = 0.f;

    load_stage(0, 0); CP_COMMIT();
    load_stage(1, 1); CP_COMMIT();

    const int rl16 = lane & 15;
    const int ksel = lane >> 4;
    uint32_t aOff[4]; int aSwz[4];
    uint32_t bOff[2]; int bSwz[2];
#pragma unroll
    for (int mt = 0; mt < 4; ++mt) {
        const int r = warp_m * 64 + mt * 16 + rl16;
        aOff[mt] = r * 128; aSwz[mt] = r & 7;
    }
#pragma unroll
    for (int p = 0; p < 2; ++p) {
        const int r = warp_n * 32 + p * 16 + rl16;
        bOff[p] = 16384 + r * 128; bSwz[p] = r & 7;
    }

    for (int kt = 0; kt < 64; ++kt) {
        const int s = kt % 3;
        CP_WAIT1();
        __syncthreads();
        if (kt + 2 < 64) load_stage(kt + 2, (kt + 2) % 3);
        CP_COMMIT();

        const uint32_t stage = sbase + s * K1_STAGE;
#pragma unroll
        for (int ks = 0; ks < 4; ++ks) {
            const int chunk = ks * 2 + ksel;
            uint32_t a[4][4], b[2][4];
#pragma unroll
            for (int mt = 0; mt < 4; ++mt)
                LDMATRIX_X4(a[mt], stage + aOff[mt] + ((chunk ^ aSwz[mt]) << 4));
#pragma unroll
            for (int p = 0; p < 2; ++p)
                LDMATRIX_X4(b[p], stage + bOff[p] + ((chunk ^ bSwz[p]) << 4));
#pragma unroll
            for (int mt = 0; mt < 4; ++mt)
#pragma unroll
                for (int nt = 0; nt < 4; ++nt)
                    mma_f16(acc[mt][nt], a[mt],
                            b[nt >> 1][nt & 1], b[nt >> 1][2 + (nt & 1)]);
        }
    }

    // epilogue: fp32 gating + tanh; also emit fp16 h_t copy for k2
    const int g = lane >> 2, tig = lane & 3;
    const int mBase = m0 + warp_m * 64;
    const int nBase = n0 + warp_n * 32;
#pragma unroll
    for (int nt = 0; nt < 4; ++nt) {
        const int n = nBase + nt * 8 + tig * 2;
        const float om0 = 1.f / (1.f + __expf(alpha_raw[n]));
        const float om1 = 1.f / (1.f + __expf(alpha_raw[n + 1]));
        const float bi0 = U_b[n], bi1 = U_b[n + 1];
#pragma unroll
        for (int mt = 0; mt < 4; ++mt) {
            int m = mBase + mt * 16 + g;
            float2 hp = *(const float2*)(h_prev + (size_t)m * NH + n);
            float2 o;
            o.x = om0 * hp.x + tanhf(acc[mt][nt][0] + bi0);
            o.y = om1 * hp.y + tanhf(acc[mt][nt][1] + bi1);
            *(float2*)(h_t + (size_t)m * NH + n) = o;
            *(__half2*)(g_hth + (size_t)m * NH + n) = __floats2half2_rn(o.x, o.y);
            m += 8;
            hp = *(const float2*)(h_prev + (size_t)m * NH + n);
            o.x = om0 * hp.x + tanhf(acc[mt][nt][2] + bi0);
            o.y = om1 * hp.y + tanhf(acc[mt][nt][3] + bi1);
            *(float2*)(h_t + (size_t)m * NH + n) = o;
            *(__half2*)(g_hth + (size_t)m * NH + n) = __floats2half2_rn(o.x, o.y);
        }
    }
}

// ---------------------------------------------------------------------------
// Kernel 2 (fp16 mma): q/k/v = h_t @ W{Q,K,V}^T  (M=8192, N=64, K=2048)
// BM=128, BN=64, BK=64, 256 thr (8 warps 4x2), warp tile 32x32, 3 stages.
// ---------------------------------------------------------------------------
#define K2_STAGE 24576                         // A 16KB + B 8KB
#define K2_SMEM (3 * K2_STAGE)

__global__ __launch_bounds__(256, 1)
void k2_qkv_f16()
{
    extern __shared__ char sm[];
    const uint32_t sbase = smem_u32(sm);

    const int tid  = threadIdx.x;
    const int wid  = tid >> 5;
    const int lane = tid & 31;
    const int warp_m = wid & 3;
    const int warp_n = wid >> 2;
    const int m0 = blockIdx.x * 128;
    const int z  = blockIdx.z;
    const __half* Bsrc = (z == 0) ? g_wq16 : (z == 1) ? g_wk16 : g_wv16;
    float* out         = (z == 0) ? g_q : (z == 1) ? g_k : g_v;

    auto load_stage = [&](int kt, int s) {
        const int k0 = kt << 6;
        const uint32_t sa = sbase + s * K2_STAGE;
        const uint32_t sb = sa + 16384;
#pragma unroll
        for (int i = 0; i < 4; ++i) {
            const int id = tid + 256 * i;
            const int row = id >> 3, c = id & 7;
            CP_ASYNC16(sa + row * 128 + ((c ^ (row & 7)) << 4),
                       g_hth + (size_t)(m0 + row) * NH + k0 + c * 8);
        }
#pragma unroll
        for (int i = 0; i < 2; ++i) {
            const int id = tid + 256 * i;
            const int row = id >> 3, c = id & 7;
            CP_ASYNC16(sb + row * 128 + ((c ^ (row & 7)) << 4),
                       Bsrc + (size_t)row * NH + k0 + c * 8);
        }
    };

    float acc[2][4][4];
#pragma unroll
    for (int a = 0; a < 2; ++a)
#pragma unroll
        for (int b = 0; b < 4; ++b)
#pragma unroll
            for (int d = 0; d < 4; ++d) acc[a][b][d] = 0.f;

    load_stage(0, 0); CP_COMMIT();
    load_stage(1, 1); CP_COMMIT();

    const int rl16 = lane & 15;
    const int ksel = lane >> 4;
    uint32_t aOff[2]; int aSwz[2];
    uint32_t bOff[2]; int bSwz[2];
#pragma unroll
    for (int mt = 0; mt < 2; ++mt) {
        const int r = warp_m * 32 + mt * 16 + rl16;
        aOff[mt] = r * 128; aSwz[mt] = r & 7;
    }
#pragma unroll
    for (int p = 0; p < 2; ++p) {
        const int r = warp_n * 32 + p * 16 + rl16;
        bOff[p] = 16384 + r * 128; bSwz[p] = r & 7;
    }

    for (int kt = 0; kt < 32; ++kt) {
        const int s = kt % 3;
        CP_WAIT1();
        __syncthreads();
        if (kt + 2 < 32) load_stage(kt + 2, (kt + 2) % 3);
        CP_COMMIT();

        const uint32_t stage = sbase + s * K2_STAGE;
#pragma unroll
        for (int ks = 0; ks < 4; ++ks) {
            const int chunk = ks * 2 + ksel;
            uint32_t a[2][4], b[2][4];
#pragma unroll
            for (int mt = 0; mt < 2; ++mt)
                LDMATRIX_X4(a[mt], stage + aOff[mt] + ((chunk ^ aSwz[mt]) << 4));
#pragma unroll
            for (int p = 0; p < 2; ++p)
                LDMATRIX_X4(b[p], stage + bOff[p] + ((chunk ^ bSwz[p]) << 4));
#pragma unroll
            for (int mt = 0; mt < 2; ++mt)
#pragma unroll
                for (int nt = 0; nt < 4; ++nt)
                    mma_f16(acc[mt][nt], a[mt],
                            b[nt >> 1][nt & 1], b[nt >> 1][2 + (nt & 1)]);
        }
    }

    const int g = lane >> 2, tig = lane & 3;
    const int mBase = m0 + warp_m * 32;
    const int nBase = warp_n * 32;
#pragma unroll
    for (int nt = 0; nt < 4; ++nt) {
        const int n = nBase + nt * 8 + tig * 2;
#pragma unroll
        for (int mt = 0; mt < 2; ++mt) {
            int m = mBase + mt * 16 + g;
            *(float2*)(out + (size_t)m * NR + n) =
                make_float2(acc[mt][nt][0], acc[mt][nt][1]);
            m += 8;
            *(float2*)(out + (size_t)m * NR + n) =
                make_float2(acc[mt][nt][2], acc[mt][nt][3]);
        }
    }
}

// ---------------------------------------------------------------------------
// Kernel 3: per-row outer-product softmax routing.
// ---------------------------------------------------------------------------
__global__ __launch_bounds__(256)
void k3_attn()
{
    const int warp = (blockIdx.x * blockDim.x + threadIdx.x) >> 5;
    const int lane = threadIdx.x & 31;
    if (warp >= NB) return;

    const float* q = g_q + (size_t)warp * NR;
    const float* k = g_k + (size_t)warp * NR;
    const float* v = g_v + (size_t)warp * NR;
    const unsigned full = 0xffffffffu;

    const float q0 = q[lane], q1 = q[lane + 32];
    const float k0 = k[lane], k1 = k[lane + 32];
    const float v0 = v[lane], v1 = v[lane + 32];

    float kmx = fmaxf(k0, k1), kmn = fminf(k0, k1);
#pragma unroll
    for (int o = 16; o; o >>= 1) {
        kmx = fmaxf(kmx, __shfl_xor_sync(full, kmx, o));
        kmn = fminf(kmn, __shfl_xor_sync(full, kmn, o));
    }
    const float m0 = 0.125f * q0 * ((q0 >= 0.f) ? kmx : kmn);
    const float m1 = 0.125f * q1 * ((q1 >= 0.f) ? kmx : kmn);

    float se0 = 0.f, sd0 = 0.f, se1 = 0.f, sd1 = 0.f;
#pragma unroll 8
    for (int j = 0; j < 32; ++j) {
        const float kj = __shfl_sync(full, k0, j);
        const float vj = __shfl_sync(full, v0, j);
        const float e0 = __expf(fmaf(0.125f * q0, kj, -m0));
        const float e1 = __expf(fmaf(0.125f * q1, kj, -m1));
        se0 += e0; sd0 = fmaf(e0, vj, sd0);
        se1 += e1; sd1 = fmaf(e1, vj, sd1);
    }
#pragma unroll 8
    for (int j = 0; j < 32; ++j) {
        const float kj = __shfl_sync(full, k1, j);
        const float vj = __shfl_sync(full, v1, j);
        const float e0 = __expf(fmaf(0.125f * q0, kj, -m0));
        const float e1 = __expf(fmaf(0.125f * q1, kj, -m1));
        se0 += e0; sd0 = fmaf(e0, vj, sd0);
        se1 += e1; sd1 = fmaf(e1, vj, sd1);
    }

    g_rv16[(size_t)warp * NR + lane]      = __float2half(sd0 / se0);
    g_rv16[(size_t)warp * NR + 32 + lane] = __float2half(sd1 / se1);
}

// ---------------------------------------------------------------------------
// Kernel 4 (fp16 mma, single K-shot): y = gamma*(rv @ WO^T) + x_t
// ---------------------------------------------------------------------------
__global__ __launch_bounds__(512, 1)
void k4_out_f16(const float* __restrict__ x_t,
                const float* __restrict__ gamma,
                float* __restrict__ y)
{
    __shared__ __align__(16) char sm4[49152];
    const uint32_t sbase = smem_u32(sm4);

    const int tid  = threadIdx.x;
    const int wid  = tid >> 5;
    const int lane = tid & 31;
    const int warp_m = wid & 1;
    const int warp_n = wid >> 1;
    const int m0 = blockIdx.y * 128;
    const int n0 = blockIdx.x * 256;

#pragma unroll
    for (int i = 0; i < 2; ++i) {
        const int id = tid + 512 * i;
        const int row = id >> 3, c = id & 7;
        CP_ASYNC16(sbase + row * 128 + ((c ^ (row & 7)) << 4),
                   g_rv16 + (size_t)(m0 + row) * NR + c * 8);
    }
#pragma unroll
    for (int i = 0; i < 4; ++i) {
        const int id = tid + 512 * i;
        const int row = id >> 3, c = id & 7;
        CP_ASYNC16(sbase + 16384 + row * 128 + ((c ^ (row & 7)) << 4),
                   g_wo16 + (size_t)(n0 + row) * NR + c * 8);
    }
    CP_COMMIT(); CP_WAIT0();
    __syncthreads();

    const int rl16 = lane & 15;
    const int ksel = lane >> 4;
    float acc[4][4][4];
#pragma unroll
    for (int a = 0; a < 4; ++a)
#pragma unroll
        for (int b = 0; b < 4; ++b)
#pragma unroll
            for (int d = 0; d < 4; ++d) acc[a][b][d] = 0.f;

#pragma unroll
    for (int ks = 0; ks < 4; ++ks) {
        const int chunk = ks * 2 + ksel;
        uint32_t a[4][4], b[2][4];
#pragma unroll
        for (int mt = 0; mt < 4; ++mt) {
            const int r = warp_m * 64 + mt * 16 + rl16;
            LDMATRIX_X4(a[mt], sbase + r * 128 + ((chunk ^ (r & 7)) << 4));
        }
#pragma unroll
        for (int p = 0; p < 2; ++p) {
            const int r = warp_n * 32 + p * 16 + rl16;
            LDMATRIX_X4(b[p], sbase + 16384 + r * 128 + ((chunk ^ (r & 7)) << 4));
        }
#pragma unroll
        for (int mt = 0; mt < 4; ++mt)
#pragma unroll
            for (int nt = 0; nt < 4; ++nt)
                mma_f16(acc[mt][nt], a[mt],
                        b[nt >> 1][nt & 1], b[nt >> 1][2 + (nt & 1)]);
    }

    const float gm = gamma[0];
    const int g = lane >> 2, tig = lane & 3;
    const int mBase = m0 + warp_m * 64;
    const int nBase = n0 + warp_n * 32;
#pragma unroll
    for (int nt = 0; nt < 4; ++nt) {
        const int n = nBase + nt * 8 + tig * 2;
#pragma unroll
        for (int mt = 0; mt < 4; ++mt) {
            int m = mBase + mt * 16 + g;
            float2 xv = *(const float2*)(x_t + (size_t)m * NH + n);
            float2 o;
            o.x = fmaf(gm, acc[mt][nt][0], xv.x);
            o.y = fmaf(gm, acc[mt][nt][1], xv.y);
            *(float2*)(y + (size_t)m * NH + n) = o;
            m += 8;
            xv = *(const float2*)(x_t + (size_t)m * NH + n);
            o.x = fmaf(gm, acc[mt][nt][2], xv.x);
            o.y = fmaf(gm, acc[mt][nt][3], xv.y);
            *(float2*)(y + (size_t)m * NH + n) = o;
        }
    }
}

// ---------------------------------------------------------------------------
extern "C" void kernel_launch(void* const* d_in, const int* in_sizes, int n_in,
                              void* d_out, int out_size)
{
    const float* h_prev    = (const float*)d_in[0];
    const float* x_t       = (const float*)d_in[1];
    const float* U_w       = (const float*)d_in[2];
    const float* U_b       = (const float*)d_in[3];
    const float* W_w       = (const float*)d_in[4];
    const float* alpha_raw = (const float*)d_in[5];
    const float* WQ        = (const float*)d_in[6];
    const float* WK        = (const float*)d_in[7];
    const float* WV        = (const float*)d_in[8];
    const float* WO        = (const float*)d_in[9];
    const float* gamma     = (const float*)d_in[10];

    float* h_t = (float*)d_out;
    float* y_t = h_t + (size_t)NB * NH;

    cudaFuncSetAttribute(k1_liquid_f16,
                         cudaFuncAttributeMaxDynamicSharedMemorySize, K1_SMEM);
    cudaFuncSetAttribute(k2_qkv_f16,
                         cudaFuncAttributeMaxDynamicSharedMemorySize, K2_SMEM);

    cvt_all<<<(CVT_TOTAL4 + 255) / 256, 256>>>(h_prev, x_t, W_w, U_w,
                                               WQ, WK, WV, WO);

    dim3 g1(NH / 128, NB / 128);                      // (16, 64) = 1024 CTAs
    k1_liquid_f16<<<g1, 256, K1_SMEM>>>(h_prev, U_b, alpha_raw, h_t);

    dim3 g2(NB / 128, 1, 3);                          // (64, 1, 3)
    k2_qkv_f16<<<g2, 256, K2_SMEM>>>();

    k3_attn<<<NB / 8, 256>>>();

    dim3 g4(NH / 256, NB / 128);                      // (8, 64)
    k4_out_f16<<<g4, 512>>>(x_t, gamma, y_t);
}

// round 7
// speedup vs baseline: 1.2246x; 1.0043x over previous
#include <cuda_runtime.h>
#include <cuda_fp16.h>
#include <math.h>
#include <stdint.h>

#define NB 8192
#define NH 2048
#define NR 64

// fp32 scratch
__device__ float g_q[NB * NR];
__device__ float g_k[NB * NR];
__device__ float g_v[NB * NR];
// fp16 scratch
__device__ __half g_hp16[NB * NH];
__device__ __half g_xt16[NB * NH];
__device__ __half g_ww16[NH * NH];
__device__ __half g_uw16[NH * NH];
__device__ __half g_wq16[NR * NH];
__device__ __half g_wk16[NR * NH];
__device__ __half g_wv16[NR * NH];
__device__ __half g_wo16[NH * NR];
__device__ __half g_hth[NB * NH];      // h_t fp16 (k1 -> k2)
__device__ __half g_rv16[NB * NR];     // routed_v fp16 (k3 -> k4)

// ---------------------------------------------------------------------------
// helpers (sm_80-compatible; NO 'a'-suffix features)
// ---------------------------------------------------------------------------
__device__ __forceinline__ uint32_t smem_u32(const void* p) {
    uint32_t a;
    asm("{ .reg .u64 t; cvta.to.shared.u64 t, %1; cvt.u32.u64 %0, t; }"
        : "=r"(a) : "l"(p));
    return a;
}
#define LDMATRIX_X4(r, addr)                                                    \
    asm volatile("ldmatrix.sync.aligned.m8n8.x4.shared.b16 {%0,%1,%2,%3}, [%4];"\
        : "=r"((r)[0]), "=r"((r)[1]), "=r"((r)[2]), "=r"((r)[3]) : "r"(addr))

__device__ __forceinline__ void mma_f16(float c[4], const uint32_t a[4],
                                        uint32_t b0, uint32_t b1) {
    asm volatile(
        "mma.sync.aligned.m16n8k16.row.col.f32.f16.f16.f32 "
        "{%0,%1,%2,%3}, {%4,%5,%6,%7}, {%8,%9}, {%0,%1,%2,%3};"
        : "+f"(c[0]), "+f"(c[1]), "+f"(c[2]), "+f"(c[3])
        : "r"(a[0]), "r"(a[1]), "r"(a[2]), "r"(a[3]), "r"(b0), "r"(b1));
}

#define CP_ASYNC16(saddr, gptr)                                                \
    asm volatile("cp.async.cg.shared.global [%0], [%1], 16;"                   \
        :: "r"(saddr), "l"(gptr) : "memory")
#define CP_COMMIT() asm volatile("cp.async.commit_group;" ::: "memory")
#define CP_WAIT1()  asm volatile("cp.async.wait_group 1;" ::: "memory")
#define CP_WAIT0()  asm volatile("cp.async.wait_group 0;" ::: "memory")

// ---------------------------------------------------------------------------
// fused pre-pass: all fp32 -> fp16 in one kernel, 4 float4 per thread
// segments (float4 units): hp 4194304 | xt 4194304 | ww 1048576 | uw 1048576 |
//                          wq 32768 | wk 32768 | wv 32768 | wo 32768
// ---------------------------------------------------------------------------
#define CVT_TOTAL4 10616832
__global__ __launch_bounds__(256)
void cvt_all(const float* __restrict__ hp, const float* __restrict__ xt,
             const float* __restrict__ ww, const float* __restrict__ uw,
             const float* __restrict__ wq, const float* __restrict__ wk,
             const float* __restrict__ wv, const float* __restrict__ wo)
{
    const int base = blockIdx.x * 1024 + threadIdx.x;
#pragma unroll
    for (int it = 0; it < 4; ++it) {
        const int i = base + it * 256;
        if (i >= CVT_TOTAL4) return;
        const float* src; __half* dst; int off;
        if (i < 4194304)        { src = hp; dst = g_hp16; off = i; }
        else if (i < 8388608)   { src = xt; dst = g_xt16; off = i - 4194304; }
        else if (i < 9437184)   { src = ww; dst = g_ww16; off = i - 8388608; }
        else if (i < 10485760)  { src = uw; dst = g_uw16; off = i - 9437184; }
        else if (i < 10518528)  { src = wq; dst = g_wq16; off = i - 10485760; }
        else if (i < 10551296)  { src = wk; dst = g_wk16; off = i - 10518528; }
        else if (i < 10584064)  { src = wv; dst = g_wv16; off = i - 10551296; }
        else                    { src = wo; dst = g_wo16; off = i - 10584064; }
        float4 v = ((const float4*)src)[off];
        ((__half2*)dst)[2 * off]     = __floats2half2_rn(v.x, v.y);
        ((__half2*)dst)[2 * off + 1] = __floats2half2_rn(v.z, v.w);
    }
}

// ---------------------------------------------------------------------------
// Kernel 1 (fp16 mma): h_t = (1-sigmoid(alpha))*h_prev
//                            + tanh(h_prev@W_w^T + x_t@U_w^T + U_b)
// BM=128, BN=128, BK=64, 256 thr (8 warps 2x4), warp tile 64x32.
// 3-stage cp.async (96KB) -> occupancy 2; 1024 CTAs. (R6 config, at the
// legacy-HMMA issue floor — do not touch.)
// ---------------------------------------------------------------------------
#define K1_STAGE 32768
#define K1_SMEM (3 * K1_STAGE)

__global__ __launch_bounds__(256, 2)
void k1_liquid_f16(const float* __restrict__ h_prev,
                   const float* __restrict__ U_b,
                   const float* __restrict__ alpha_raw,
                   float* __restrict__ h_t)
{
    extern __shared__ char sm[];
    const uint32_t sbase = smem_u32(sm);

    const int tid  = threadIdx.x;
    const int wid  = tid >> 5;
    const int lane = tid & 31;
    const int warp_m = wid & 1;
    const int warp_n = wid >> 1;
    const int m0 = blockIdx.y * 128;
    const int n0 = blockIdx.x * 128;

    auto load_stage = [&](int kt, int s) {
        const __half* Asrc = (kt < 32) ? g_hp16 : g_xt16;
        const __half* Bsrc = (kt < 32) ? g_ww16 : g_uw16;
        const int k0 = (kt & 31) << 6;
        const uint32_t sa = sbase + s * K1_STAGE;
        const uint32_t sb = sa + 16384;
#pragma unroll
        for (int i = 0; i < 4; ++i) {
            const int id = tid + 256 * i;
            const int row = id >> 3, c = id & 7;
            CP_ASYNC16(sa + row * 128 + ((c ^ (row & 7)) << 4),
                       Asrc + (size_t)(m0 + row) * NH + k0 + c * 8);
        }
#pragma unroll
        for (int i = 0; i < 4; ++i) {
            const int id = tid + 256 * i;
            const int row = id >> 3, c = id & 7;
            CP_ASYNC16(sb + row * 128 + ((c ^ (row & 7)) << 4),
                       Bsrc + (size_t)(n0 + row) * NH + k0 + c * 8);
        }
    };

    float acc[4][4][4];
#pragma unroll
    for (int a = 0; a < 4; ++a)
#pragma unroll
        for (int b = 0; b < 4; ++b)
#pragma unroll
            for (int d = 0; d < 4; ++d) acc[a][b][d] = 0.f;

    load_stage(0, 0); CP_COMMIT();
    load_stage(1, 1); CP_COMMIT();

    const int rl16 = lane & 15;
    const int ksel = lane >> 4;
    uint32_t aOff[4]; int aSwz[4];
    uint32_t bOff[2]; int bSwz[2];
#pragma unroll
    for (int mt = 0; mt < 4; ++mt) {
        const int r = warp_m * 64 + mt * 16 + rl16;
        aOff[mt] = r * 128; aSwz[mt] = r & 7;
    }
#pragma unroll
    for (int p = 0; p < 2; ++p) {
        const int r = warp_n * 32 + p * 16 + rl16;
        bOff[p] = 16384 + r * 128; bSwz[p] = r & 7;
    }

    for (int kt = 0; kt < 64; ++kt) {
        const int s = kt % 3;
        CP_WAIT1();
        __syncthreads();
        if (kt + 2 < 64) load_stage(kt + 2, (kt + 2) % 3);
        CP_COMMIT();

        const uint32_t stage = sbase + s * K1_STAGE;
#pragma unroll
        for (int ks = 0; ks < 4; ++ks) {
            const int chunk = ks * 2 + ksel;
            uint32_t a[4][4], b[2][4];
#pragma unroll
            for (int mt = 0; mt < 4; ++mt)
                LDMATRIX_X4(a[mt], stage + aOff[mt] + ((chunk ^ aSwz[mt]) << 4));
#pragma unroll
            for (int p = 0; p < 2; ++p)
                LDMATRIX_X4(b[p], stage + bOff[p] + ((chunk ^ bSwz[p]) << 4));
#pragma unroll
            for (int mt = 0; mt < 4; ++mt)
#pragma unroll
                for (int nt = 0; nt < 4; ++nt)
                    mma_f16(acc[mt][nt], a[mt],
                            b[nt >> 1][nt & 1], b[nt >> 1][2 + (nt & 1)]);
        }
    }

    const int g = lane >> 2, tig = lane & 3;
    const int mBase = m0 + warp_m * 64;
    const int nBase = n0 + warp_n * 32;
#pragma unroll
    for (int nt = 0; nt < 4; ++nt) {
        const int n = nBase + nt * 8 + tig * 2;
        const float om0 = 1.f / (1.f + __expf(alpha_raw[n]));
        const float om1 = 1.f / (1.f + __expf(alpha_raw[n + 1]));
        const float bi0 = U_b[n], bi1 = U_b[n + 1];
#pragma unroll
        for (int mt = 0; mt < 4; ++mt) {
            int m = mBase + mt * 16 + g;
            float2 hp = *(const float2*)(h_prev + (size_t)m * NH + n);
            float2 o;
            o.x = om0 * hp.x + tanhf(acc[mt][nt][0] + bi0);
            o.y = om1 * hp.y + tanhf(acc[mt][nt][1] + bi1);
            *(float2*)(h_t + (size_t)m * NH + n) = o;
            *(__half2*)(g_hth + (size_t)m * NH + n) = __floats2half2_rn(o.x, o.y);
            m += 8;
            hp = *(const float2*)(h_prev + (size_t)m * NH + n);
            o.x = om0 * hp.x + tanhf(acc[mt][nt][2] + bi0);
            o.y = om1 * hp.y + tanhf(acc[mt][nt][3] + bi1);
            *(float2*)(h_t + (size_t)m * NH + n) = o;
            *(__half2*)(g_hth + (size_t)m * NH + n) = __floats2half2_rn(o.x, o.y);
        }
    }
}

// ---------------------------------------------------------------------------
// Kernel 2 (fp16 mma): q/k/v = h_t @ W{Q,K,V}^T  (unchanged)
// ---------------------------------------------------------------------------
#define K2_STAGE 24576
#define K2_SMEM (3 * K2_STAGE)

__global__ __launch_bounds__(256, 1)
void k2_qkv_f16()
{
    extern __shared__ char sm[];
    const uint32_t sbase = smem_u32(sm);

    const int tid  = threadIdx.x;
    const int wid  = tid >> 5;
    const int lane = tid & 31;
    const int warp_m = wid & 3;
    const int warp_n = wid >> 2;
    const int m0 = blockIdx.x * 128;
    const int z  = blockIdx.z;
    const __half* Bsrc = (z == 0) ? g_wq16 : (z == 1) ? g_wk16 : g_wv16;
    float* out         = (z == 0) ? g_q : (z == 1) ? g_k : g_v;

    auto load_stage = [&](int kt, int s) {
        const int k0 = kt << 6;
        const uint32_t sa = sbase + s * K2_STAGE;
        const uint32_t sb = sa + 16384;
#pragma unroll
        for (int i = 0; i < 4; ++i) {
            const int id = tid + 256 * i;
            const int row = id >> 3, c = id & 7;
            CP_ASYNC16(sa + row * 128 + ((c ^ (row & 7)) << 4),
                       g_hth + (size_t)(m0 + row) * NH + k0 + c * 8);
        }
#pragma unroll
        for (int i = 0; i < 2; ++i) {
            const int id = tid + 256 * i;
            const int row = id >> 3, c = id & 7;
            CP_ASYNC16(sb + row * 128 + ((c ^ (row & 7)) << 4),
                       Bsrc + (size_t)row * NH + k0 + c * 8);
        }
    };

    float acc[2][4][4];
#pragma unroll
    for (int a = 0; a < 2; ++a)
#pragma unroll
        for (int b = 0; b < 4; ++b)
#pragma unroll
            for (int d = 0; d < 4; ++d) acc[a][b][d] = 0.f;

    load_stage(0, 0); CP_COMMIT();
    load_stage(1, 1); CP_COMMIT();

    const int rl16 = lane & 15;
    const int ksel = lane >> 4;
    uint32_t aOff[2]; int aSwz[2];
    uint32_t bOff[2]; int bSwz[2];
#pragma unroll
    for (int mt = 0; mt < 2; ++mt) {
        const int r = warp_m * 32 + mt * 16 + rl16;
        aOff[mt] = r * 128; aSwz[mt] = r & 7;
    }
#pragma unroll
    for (int p = 0; p < 2; ++p) {
        const int r = warp_n * 32 + p * 16 + rl16;
        bOff[p] = 16384 + r * 128; bSwz[p] = r & 7;
    }

    for (int kt = 0; kt < 32; ++kt) {
        const int s = kt % 3;
        CP_WAIT1();
        __syncthreads();
        if (kt + 2 < 32) load_stage(kt + 2, (kt + 2) % 3);
        CP_COMMIT();

        const uint32_t stage = sbase + s * K2_STAGE;
#pragma unroll
        for (int ks = 0; ks < 4; ++ks) {
            const int chunk = ks * 2 + ksel;
            uint32_t a[2][4], b[2][4];
#pragma unroll
            for (int mt = 0; mt < 2; ++mt)
                LDMATRIX_X4(a[mt], stage + aOff[mt] + ((chunk ^ aSwz[mt]) << 4));
#pragma unroll
            for (int p = 0; p < 2; ++p)
                LDMATRIX_X4(b[p], stage + bOff[p] + ((chunk ^ bSwz[p]) << 4));
#pragma unroll
            for (int mt = 0; mt < 2; ++mt)
#pragma unroll
                for (int nt = 0; nt < 4; ++nt)
                    mma_f16(acc[mt][nt], a[mt],
                            b[nt >> 1][nt & 1], b[nt >> 1][2 + (nt & 1)]);
        }
    }

    const int g = lane >> 2, tig = lane & 3;
    const int mBase = m0 + warp_m * 32;
    const int nBase = warp_n * 32;
#pragma unroll
    for (int nt = 0; nt < 4; ++nt) {
        const int n = nBase + nt * 8 + tig * 2;
#pragma unroll
        for (int mt = 0; mt < 2; ++mt) {
            int m = mBase + mt * 16 + g;
            *(float2*)(out + (size_t)m * NR + n) =
                make_float2(acc[mt][nt][0], acc[mt][nt][1]);
            m += 8;
            *(float2*)(out + (size_t)m * NR + n) =
                make_float2(acc[mt][nt][2], acc[mt][nt][3]);
        }
    }
}

// ---------------------------------------------------------------------------
// Kernel 3: per-row outer-product softmax routing, NO max subtraction.
// Scores |s| <= ~6 so exp is fp32-safe; result is mathematically identical.
// ---------------------------------------------------------------------------
__global__ __launch_bounds__(256)
void k3_attn()
{
    const int warp = (blockIdx.x * blockDim.x + threadIdx.x) >> 5;
    const int lane = threadIdx.x & 31;
    if (warp >= NB) return;

    const float* q = g_q + (size_t)warp * NR;
    const float* k = g_k + (size_t)warp * NR;
    const float* v = g_v + (size_t)warp * NR;
    const unsigned full = 0xffffffffu;

    const float q0s = 0.125f * q[lane];
    const float q1s = 0.125f * q[lane + 32];
    const float k0 = k[lane], k1 = k[lane + 32];
    const float v0 = v[lane], v1 = v[lane + 32];

    float se0 = 0.f, sd0 = 0.f, se1 = 0.f, sd1 = 0.f;
#pragma unroll 8
    for (int j = 0; j < 32; ++j) {
        const float kj = __shfl_sync(full, k0, j);
        const float vj = __shfl_sync(full, v0, j);
        const float e0 = __expf(q0s * kj);
        const float e1 = __expf(q1s * kj);
        se0 += e0; sd0 = fmaf(e0, vj, sd0);
        se1 += e1; sd1 = fmaf(e1, vj, sd1);
    }
#pragma unroll 8
    for (int j = 0; j < 32; ++j) {
        const float kj = __shfl_sync(full, k1, j);
        const float vj = __shfl_sync(full, v1, j);
        const float e0 = __expf(q0s * kj);
        const float e1 = __expf(q1s * kj);
        se0 += e0; sd0 = fmaf(e0, vj, sd0);
        se1 += e1; sd1 = fmaf(e1, vj, sd1);
    }

    g_rv16[(size_t)warp * NR + lane]      = __float2half(sd0 / se0);
    g_rv16[(size_t)warp * NR + 32 + lane] = __float2half(sd1 / se1);
}

// ---------------------------------------------------------------------------
// Kernel 4 (fp16 mma, single K-shot): y = gamma*(rv @ WO^T) + x_t
// Re-tiled: BM=128, BN=128, 256 thr (2x4 warps, warp tile 64x32), 32KB smem,
// 1024 CTAs, occ ~4 -> latency-hiding for the single-shot tile loads.
// ---------------------------------------------------------------------------
__global__ __launch_bounds__(256)
void k4_out_f16(const float* __restrict__ x_t,
                const float* __restrict__ gamma,
                float* __restrict__ y)
{
    __shared__ __align__(16) char sm4[32768];
    const uint32_t sbase = smem_u32(sm4);

    const int tid  = threadIdx.x;
    const int wid  = tid >> 5;
    const int lane = tid & 31;
    const int warp_m = wid & 1;       // 2 warps over M=128
    const int warp_n = wid >> 1;      // 4 warps over N=128
    const int m0 = blockIdx.y * 128;
    const int n0 = blockIdx.x * 128;

    // A: rv 128x64 halfs (16KB); B: WO 128x64 halfs (16KB)
#pragma unroll
    for (int i = 0; i < 4; ++i) {
        const int id = tid + 256 * i;
        const int row = id >> 3, c = id & 7;
        CP_ASYNC16(sbase + row * 128 + ((c ^ (row & 7)) << 4),
                   g_rv16 + (size_t)(m0 + row) * NR + c * 8);
    }
#pragma unroll
    for (int i = 0; i < 4; ++i) {
        const int id = tid + 256 * i;
        const int row = id >> 3, c = id & 7;
        CP_ASYNC16(sbase + 16384 + row * 128 + ((c ^ (row & 7)) << 4),
                   g_wo16 + (size_t)(n0 + row) * NR + c * 8);
    }
    CP_COMMIT(); CP_WAIT0();
    __syncthreads();

    const int rl16 = lane & 15;
    const int ksel = lane >> 4;
    float acc[4][4][4];
#pragma unroll
    for (int a = 0; a < 4; ++a)
#pragma unroll
        for (int b = 0; b < 4; ++b)
#pragma unroll
            for (int d = 0; d < 4; ++d) acc[a][b][d] = 0.f;

#pragma unroll
    for (int ks = 0; ks < 4; ++ks) {
        const int chunk = ks * 2 + ksel;
        uint32_t a[4][4], b[2][4];
#pragma unroll
        for (int mt = 0; mt < 4; ++mt) {
            const int r = warp_m * 64 + mt * 16 + rl16;
            LDMATRIX_X4(a[mt], sbase + r * 128 + ((chunk ^ (r & 7)) << 4));
        }
#pragma unroll
        for (int p = 0; p < 2; ++p) {
            const int r = warp_n * 32 + p * 16 + rl16;
            LDMATRIX_X4(b[p], sbase + 16384 + r * 128 + ((chunk ^ (r & 7)) << 4));
        }
#pragma unroll
        for (int mt = 0; mt < 4; ++mt)
#pragma unroll
            for (int nt = 0; nt < 4; ++nt)
                mma_f16(acc[mt][nt], a[mt],
                        b[nt >> 1][nt & 1], b[nt >> 1][2 + (nt & 1)]);
    }

    const float gm = gamma[0];
    const int g = lane >> 2, tig = lane & 3;
    const int mBase = m0 + warp_m * 64;
    const int nBase = n0 + warp_n * 32;
#pragma unroll
    for (int nt = 0; nt < 4; ++nt) {
        const int n = nBase + nt * 8 + tig * 2;
#pragma unroll
        for (int mt = 0; mt < 4; ++mt) {
            int m = mBase + mt * 16 + g;
            float2 xv = *(const float2*)(x_t + (size_t)m * NH + n);
            float2 o;
            o.x = fmaf(gm, acc[mt][nt][0], xv.x);
            o.y = fmaf(gm, acc[mt][nt][1], xv.y);
            *(float2*)(y + (size_t)m * NH + n) = o;
            m += 8;
            xv = *(const float2*)(x_t + (size_t)m * NH + n);
            o.x = fmaf(gm, acc[mt][nt][2], xv.x);
            o.y = fmaf(gm, acc[mt][nt][3], xv.y);
            *(float2*)(y + (size_t)m * NH + n) = o;
        }
    }
}

// ---------------------------------------------------------------------------
extern "C" void kernel_launch(void* const* d_in, const int* in_sizes, int n_in,
                              void* d_out, int out_size)
{
    const float* h_prev    = (const float*)d_in[0];
    const float* x_t       = (const float*)d_in[1];
    const float* U_w       = (const float*)d_in[2];
    const float* U_b       = (const float*)d_in[3];
    const float* W_w       = (const float*)d_in[4];
    const float* alpha_raw = (const float*)d_in[5];
    const float* WQ        = (const float*)d_in[6];
    const float* WK        = (const float*)d_in[7];
    const float* WV        = (const float*)d_in[8];
    const float* WO        = (const float*)d_in[9];
    const float* gamma     = (const float*)d_in[10];

    float* h_t = (float*)d_out;
    float* y_t = h_t + (size_t)NB * NH;

    cudaFuncSetAttribute(k1_liquid_f16,
                         cudaFuncAttributeMaxDynamicSharedMemorySize, K1_SMEM);
    cudaFuncSetAttribute(k2_qkv_f16,
                         cudaFuncAttributeMaxDynamicSharedMemorySize, K2_SMEM);

    cvt_all<<<(CVT_TOTAL4 + 1023) / 1024, 256>>>(h_prev, x_t, W_w, U_w,
                                                 WQ, WK, WV, WO);

    dim3 g1(NH / 128, NB / 128);                      // (16, 64) = 1024 CTAs
    k1_liquid_f16<<<g1, 256, K1_SMEM>>>(h_prev, U_b, alpha_raw, h_t);

    dim3 g2(NB / 128, 1, 3);                          // (64, 1, 3)
    k2_qkv_f16<<<g2, 256, K2_SMEM>>>();

    k3_attn<<<NB / 8, 256>>>();

    dim3 g4(NH / 128, NB / 128);                      // (16, 64) = 1024 CTAs
    k4_out_f16<<<g4, 256>>>(x_t, gamma, y_t);
}

// round 8
// speedup vs baseline: 1.2441x; 1.0160x over previous
#include <cuda_runtime.h>
#include <cuda_fp16.h>
#include <math.h>
#include <stdint.h>

#define NB 8192
#define NH 2048
#define NR 64

// fp16 scratch
__device__ __half g_hp16[NB * NH];
__device__ __half g_xt16[NB * NH];
__device__ __half g_ww16[NH * NH];
__device__ __half g_uw16[NH * NH];
__device__ __half g_wqkv16[3 * NR * NH];   // rows 0-63 WQ | 64-127 WK | 128-191 WV
__device__ __half g_wo16[NH * NR];
__device__ __half g_hth[NB * NH];          // h_t fp16 (k1 -> k234)

// ---------------------------------------------------------------------------
// helpers (sm_80-compatible; NO 'a'-suffix features)
// ---------------------------------------------------------------------------
__device__ __forceinline__ uint32_t smem_u32(const void* p) {
    uint32_t a;
    asm("{ .reg .u64 t; cvta.to.shared.u64 t, %1; cvt.u32.u64 %0, t; }"
        : "=r"(a) : "l"(p));
    return a;
}
#define LDMATRIX_X4(r, addr)                                                    \
    asm volatile("ldmatrix.sync.aligned.m8n8.x4.shared.b16 {%0,%1,%2,%3}, [%4];"\
        : "=r"((r)[0]), "=r"((r)[1]), "=r"((r)[2]), "=r"((r)[3]) : "r"(addr))

__device__ __forceinline__ void mma_f16(float c[4], const uint32_t a[4],
                                        uint32_t b0, uint32_t b1) {
    asm volatile(
        "mma.sync.aligned.m16n8k16.row.col.f32.f16.f16.f32 "
        "{%0,%1,%2,%3}, {%4,%5,%6,%7}, {%8,%9}, {%0,%1,%2,%3};"
        : "+f"(c[0]), "+f"(c[1]), "+f"(c[2]), "+f"(c[3])
        : "r"(a[0]), "r"(a[1]), "r"(a[2]), "r"(a[3]), "r"(b0), "r"(b1));
}

#define CP_ASYNC16(saddr, gptr)                                                \
    asm volatile("cp.async.cg.shared.global [%0], [%1], 16;"                   \
        :: "r"(saddr), "l"(gptr) : "memory")
#define CP_COMMIT() asm volatile("cp.async.commit_group;" ::: "memory")
#define CP_WAIT1()  asm volatile("cp.async.wait_group 1;" ::: "memory")
#define CP_WAIT0()  asm volatile("cp.async.wait_group 0;" ::: "memory")

__device__ __forceinline__ void sts_u16(uint32_t addr, uint16_t v) {
    asm volatile("st.shared.u16 [%0], %1;" :: "r"(addr), "h"(v));
}

// ---------------------------------------------------------------------------
// fused pre-pass: all fp32 -> fp16 in one kernel, 4 float4 per thread
// ---------------------------------------------------------------------------
#define CVT_TOTAL4 10616832
__global__ __launch_bounds__(256)
void cvt_all(const float* __restrict__ hp, const float* __restrict__ xt,
             const float* __restrict__ ww, const float* __restrict__ uw,
             const float* __restrict__ wq, const float* __restrict__ wk,
             const float* __restrict__ wv, const float* __restrict__ wo)
{
    const int base = blockIdx.x * 1024 + threadIdx.x;
#pragma unroll
    for (int it = 0; it < 4; ++it) {
        const int i = base + it * 256;
        if (i >= CVT_TOTAL4) return;
        const float* src; __half* dst; int off;
        if (i < 4194304)        { src = hp; dst = g_hp16; off = i; }
        else if (i < 8388608)   { src = xt; dst = g_xt16; off = i - 4194304; }
        else if (i < 9437184)   { src = ww; dst = g_ww16; off = i - 8388608; }
        else if (i < 10485760)  { src = uw; dst = g_uw16; off = i - 9437184; }
        else if (i < 10518528)  { src = wq; dst = g_wqkv16;              off = i - 10485760; }
        else if (i < 10551296)  { src = wk; dst = g_wqkv16 + 64 * NH;    off = i - 10518528; }
        else if (i < 10584064)  { src = wv; dst = g_wqkv16 + 128 * NH;   off = i - 10551296; }
        else                    { src = wo; dst = g_wo16;                off = i - 10584064; }
        float4 v = ((const float4*)src)[off];
        ((__half2*)dst)[2 * off]     = __floats2half2_rn(v.x, v.y);
        ((__half2*)dst)[2 * off + 1] = __floats2half2_rn(v.z, v.w);
    }
}

// ---------------------------------------------------------------------------
// Kernel 1 (fp16 mma): h_t = (1-sigmoid(alpha))*h_prev
//                            + tanh(h_prev@W_w^T + x_t@U_w^T + U_b)
// BM=128, BN=128, BK=64, 256 thr, 3-stage cp.async, occ 2, 1024 CTAs.
// At the legacy-HMMA issue floor (~540 MAC/cyc/SM) — frozen since R6.
// ---------------------------------------------------------------------------
#define K1_STAGE 32768
#define K1_SMEM (3 * K1_STAGE)

__global__ __launch_bounds__(256, 2)
void k1_liquid_f16(const float* __restrict__ h_prev,
                   const float* __restrict__ U_b,
                   const float* __restrict__ alpha_raw,
                   float* __restrict__ h_t)
{
    extern __shared__ char sm[];
    const uint32_t sbase = smem_u32(sm);

    const int tid  = threadIdx.x;
    const int wid  = tid >> 5;
    const int lane = tid & 31;
    const int warp_m = wid & 1;
    const int warp_n = wid >> 1;
    const int m0 = blockIdx.y * 128;
    const int n0 = blockIdx.x * 128;

    auto load_stage = [&](int kt, int s) {
        const __half* Asrc = (kt < 32) ? g_hp16 : g_xt16;
        const __half* Bsrc = (kt < 32) ? g_ww16 : g_uw16;
        const int k0 = (kt & 31) << 6;
        const uint32_t sa = sbase + s * K1_STAGE;
        const uint32_t sb = sa + 16384;
#pragma unroll
        for (int i = 0; i < 4; ++i) {
            const int id = tid + 256 * i;
            const int row = id >> 3, c = id & 7;
            CP_ASYNC16(sa + row * 128 + ((c ^ (row & 7)) << 4),
                       Asrc + (size_t)(m0 + row) * NH + k0 + c * 8);
        }
#pragma unroll
        for (int i = 0; i < 4; ++i) {
            const int id = tid + 256 * i;
            const int row = id >> 3, c = id & 7;
            CP_ASYNC16(sb + row * 128 + ((c ^ (row & 7)) << 4),
                       Bsrc + (size_t)(n0 + row) * NH + k0 + c * 8);
        }
    };

    float acc[4][4][4];
#pragma unroll
    for (int a = 0; a < 4; ++a)
#pragma unroll
        for (int b = 0; b < 4; ++b)
#pragma unroll
            for (int d = 0; d < 4; ++d) acc[a][b][d] = 0.f;

    load_stage(0, 0); CP_COMMIT();
    load_stage(1, 1); CP_COMMIT();

    const int rl16 = lane & 15;
    const int ksel = lane >> 4;
    uint32_t aOff[4]; int aSwz[4];
    uint32_t bOff[2]; int bSwz[2];
#pragma unroll
    for (int mt = 0; mt < 4; ++mt) {
        const int r = warp_m * 64 + mt * 16 + rl16;
        aOff[mt] = r * 128; aSwz[mt] = r & 7;
    }
#pragma unroll
    for (int p = 0; p < 2; ++p) {
        const int r = warp_n * 32 + p * 16 + rl16;
        bOff[p] = 16384 + r * 128; bSwz[p] = r & 7;
    }

    for (int kt = 0; kt < 64; ++kt) {
        const int s = kt % 3;
        CP_WAIT1();
        __syncthreads();
        if (kt + 2 < 64) load_stage(kt + 2, (kt + 2) % 3);
        CP_COMMIT();

        const uint32_t stage = sbase + s * K1_STAGE;
#pragma unroll
        for (int ks = 0; ks < 4; ++ks) {
            const int chunk = ks * 2 + ksel;
            uint32_t a[4][4], b[2][4];
#pragma unroll
            for (int mt = 0; mt < 4; ++mt)
                LDMATRIX_X4(a[mt], stage + aOff[mt] + ((chunk ^ aSwz[mt]) << 4));
#pragma unroll
            for (int p = 0; p < 2; ++p)
                LDMATRIX_X4(b[p], stage + bOff[p] + ((chunk ^ bSwz[p]) << 4));
#pragma unroll
            for (int mt = 0; mt < 4; ++mt)
#pragma unroll
                for (int nt = 0; nt < 4; ++nt)
                    mma_f16(acc[mt][nt], a[mt],
                            b[nt >> 1][nt & 1], b[nt >> 1][2 + (nt & 1)]);
        }
    }

    const int g = lane >> 2, tig = lane & 3;
    const int mBase = m0 + warp_m * 64;
    const int nBase = n0 + warp_n * 32;
#pragma unroll
    for (int nt = 0; nt < 4; ++nt) {
        const int n = nBase + nt * 8 + tig * 2;
        const float om0 = 1.f / (1.f + __expf(alpha_raw[n]));
        const float om1 = 1.f / (1.f + __expf(alpha_raw[n + 1]));
        const float bi0 = U_b[n], bi1 = U_b[n + 1];
#pragma unroll
        for (int mt = 0; mt < 4; ++mt) {
            int m = mBase + mt * 16 + g;
            float2 hp = *(const float2*)(h_prev + (size_t)m * NH + n);
            float2 o;
            o.x = om0 * hp.x + tanhf(acc[mt][nt][0] + bi0);
            o.y = om1 * hp.y + tanhf(acc[mt][nt][1] + bi1);
            *(float2*)(h_t + (size_t)m * NH + n) = o;
            *(__half2*)(g_hth + (size_t)m * NH + n) = __floats2half2_rn(o.x, o.y);
            m += 8;
            hp = *(const float2*)(h_prev + (size_t)m * NH + n);
            o.x = om0 * hp.x + tanhf(acc[mt][nt][2] + bi0);
            o.y = om1 * hp.y + tanhf(acc[mt][nt][3] + bi1);
            *(float2*)(h_t + (size_t)m * NH + n) = o;
            *(__half2*)(g_hth + (size_t)m * NH + n) = __floats2half2_rn(o.x, o.y);
        }
    }
}

// ---------------------------------------------------------------------------
// Kernel 234 (fused): per 64-row batch panel,
//   A) qkv = h_t @ [WQ;WK;WV]^T   (BM=64, BN=192, K=2048, 3-stage cp.async)
//   B) routed softmax (in SMEM, identical math/order to old k3)
//   C) y = gamma*(rv @ WO^T) + x_t  (16 n-tiles, double-buffered WO)
// 128 CTAs x 256 thr.
// SMEM map (bytes): phase A: stages [0,32768),[32768,65536),[65536,98304)
//                   phase B: qkv fp32 [0, 49408) stride 193; rv [53248,61440)
//                   phase C: WO bufs [61440,77824),[77824,94208)
// ---------------------------------------------------------------------------
#define K234_STAGE 32768                     // A 8KB + B 24KB
#define K234_SMEM  98304
#define QSTR 193
#define RV_OFF 53248
#define WO_OFF 61440

__global__ __launch_bounds__(256, 1)
void k234_fused(const float* __restrict__ x_t,
                const float* __restrict__ gamma,
                float* __restrict__ y)
{
    extern __shared__ char sm[];
    const uint32_t sbase = smem_u32(sm);
    float* smf = (float*)sm;

    const int tid  = threadIdx.x;
    const int wid  = tid >> 5;
    const int lane = tid & 31;
    const int m0   = blockIdx.x * 64;
    const unsigned full = 0xffffffffu;

    const int rl16 = lane & 15;
    const int ksel = lane >> 4;
    const int g    = lane >> 2;
    const int tig  = lane & 3;

    // ================= Phase A: QKV GEMM (BM=64, BN=192) =================
    {
        const int warp_m = wid & 1;      // 2 x 32 rows
        const int warp_n = wid >> 1;     // 4 x 48 cols

        auto load_stage = [&](int kt, int s) {
            const int k0 = kt << 6;
            const uint32_t sa = sbase + s * K234_STAGE;
            const uint32_t sb = sa + 8192;
#pragma unroll
            for (int i = 0; i < 2; ++i) {            // A: 512 chunks
                const int id = tid + 256 * i;
                const int row = id >> 3, c = id & 7;
                CP_ASYNC16(sa + row * 128 + ((c ^ (row & 7)) << 4),
                           g_hth + (size_t)(m0 + row) * NH + k0 + c * 8);
            }
#pragma unroll
            for (int i = 0; i < 6; ++i) {            // B: 1536 chunks
                const int id = tid + 256 * i;
                const int row = id >> 3, c = id & 7;
                CP_ASYNC16(sb + row * 128 + ((c ^ (row & 7)) << 4),
                           g_wqkv16 + (size_t)row * NH + k0 + c * 8);
            }
        };

        float acc[2][6][4];
#pragma unroll
        for (int a = 0; a < 2; ++a)
#pragma unroll
            for (int b = 0; b < 6; ++b)
#pragma unroll
                for (int d = 0; d < 4; ++d) acc[a][b][d] = 0.f;

        load_stage(0, 0); CP_COMMIT();
        load_stage(1, 1); CP_COMMIT();

        uint32_t aOff[2]; int aSwz[2];
        uint32_t bOff[3]; int bSwz[3];
#pragma unroll
        for (int mt = 0; mt < 2; ++mt) {
            const int r = warp_m * 32 + mt * 16 + rl16;
            aOff[mt] = r * 128; aSwz[mt] = r & 7;
        }
#pragma unroll
        for (int p = 0; p < 3; ++p) {
            const int r = warp_n * 48 + p * 16 + rl16;
            bOff[p] = 8192 + r * 128; bSwz[p] = r & 7;
        }

        for (int kt = 0; kt < 32; ++kt) {
            const int s = kt % 3;
            CP_WAIT1();
            __syncthreads();
            if (kt + 2 < 32) load_stage(kt + 2, (kt + 2) % 3);
            CP_COMMIT();

            const uint32_t stage = sbase + s * K234_STAGE;
#pragma unroll
            for (int ks = 0; ks < 4; ++ks) {
                const int chunk = ks * 2 + ksel;
                uint32_t a[2][4], b[3][4];
#pragma unroll
                for (int mt = 0; mt < 2; ++mt)
                    LDMATRIX_X4(a[mt], stage + aOff[mt] + ((chunk ^ aSwz[mt]) << 4));
#pragma unroll
                for (int p = 0; p < 3; ++p)
                    LDMATRIX_X4(b[p], stage + bOff[p] + ((chunk ^ bSwz[p]) << 4));
#pragma unroll
                for (int mt = 0; mt < 2; ++mt)
#pragma unroll
                    for (int nt = 0; nt < 6; ++nt)
                        mma_f16(acc[mt][nt], a[mt],
                                b[nt >> 1][nt & 1], b[nt >> 1][2 + (nt & 1)]);
            }
        }

        CP_WAIT0();
        __syncthreads();     // all mma done; stages may be overwritten

        // write qkv (fp32) to SMEM: [64 rows][192 cols], stride QSTR
#pragma unroll
        for (int nt = 0; nt < 6; ++nt) {
            const int n = warp_n * 48 + nt * 8 + tig * 2;
#pragma unroll
            for (int mt = 0; mt < 2; ++mt) {
                int m = warp_m * 32 + mt * 16 + g;
                smf[m * QSTR + n]     = acc[mt][nt][0];
                smf[m * QSTR + n + 1] = acc[mt][nt][1];
                m += 8;
                smf[m * QSTR + n]     = acc[mt][nt][2];
                smf[m * QSTR + n + 1] = acc[mt][nt][3];
            }
        }
    }
    __syncthreads();

    // ================= Phase B: softmax routing (rows wid*8..wid*8+7) ======
    {
#pragma unroll 1
        for (int rr = 0; rr < 8; ++rr) {
            const int r = wid * 8 + rr;
            const float* qk = smf + r * QSTR;
            const float q0s = 0.125f * qk[lane];
            const float q1s = 0.125f * qk[lane + 32];
            const float k0 = qk[64 + lane],  k1 = qk[96 + lane];
            const float v0 = qk[128 + lane], v1 = qk[160 + lane];

            float se0 = 0.f, sd0 = 0.f, se1 = 0.f, sd1 = 0.f;
#pragma unroll 8
            for (int j = 0; j < 32; ++j) {
                const float kj = __shfl_sync(full, k0, j);
                const float vj = __shfl_sync(full, v0, j);
                const float e0 = __expf(q0s * kj);
                const float e1 = __expf(q1s * kj);
                se0 += e0; sd0 = fmaf(e0, vj, sd0);
                se1 += e1; sd1 = fmaf(e1, vj, sd1);
            }
#pragma unroll 8
            for (int j = 0; j < 32; ++j) {
                const float kj = __shfl_sync(full, k1, j);
                const float vj = __shfl_sync(full, v1, j);
                const float e0 = __expf(q0s * kj);
                const float e1 = __expf(q1s * kj);
                se0 += e0; sd0 = fmaf(e0, vj, sd0);
                se1 += e1; sd1 = fmaf(e1, vj, sd1);
            }

            // store rv fp16 into ldmatrix-layout SMEM (64 rows x 128B)
            const int c0 = lane, c1 = lane + 32;
            sts_u16(sbase + RV_OFF + r * 128 +
                        (((c0 >> 3) ^ (r & 7)) << 4) + (c0 & 7) * 2,
                    __half_as_ushort(__float2half(sd0 / se0)));
            sts_u16(sbase + RV_OFF + r * 128 +
                        (((c1 >> 3) ^ (r & 7)) << 4) + (c1 & 7) * 2,
                    __half_as_ushort(__float2half(sd1 / se1)));
        }
    }
    __syncthreads();

    // ================= Phase C: y = gamma*(rv @ WO^T) + x_t ================
    {
        const int warp_m = wid & 1;      // 2 x 32 rows (of 64)
        const int warp_n = wid >> 1;     // 4 x 32 cols (of 128 per tile)
        const float gm = gamma[0];

        // rv a-frags: constant across all 16 n-tiles
        uint32_t fa[2][4][4];
#pragma unroll
        for (int mt = 0; mt < 2; ++mt) {
            const int r = warp_m * 32 + mt * 16 + rl16;
#pragma unroll
            for (int ks = 0; ks < 4; ++ks) {
                const int chunk = ks * 2 + ksel;
                LDMATRIX_X4(fa[mt][ks],
                            sbase + RV_OFF + r * 128 + ((chunk ^ (r & 7)) << 4));
            }
        }

        auto load_wo = [&](int t, int buf) {
            const uint32_t sb = sbase + WO_OFF + buf * 16384;
#pragma unroll
            for (int i = 0; i < 4; ++i) {            // 1024 chunks
                const int id = tid + 256 * i;
                const int row = id >> 3, c = id & 7;
                CP_ASYNC16(sb + row * 128 + ((c ^ (row & 7)) << 4),
                           g_wo16 + (size_t)(t * 128 + row) * NR + c * 8);
            }
        };

        load_wo(0, 0); CP_COMMIT();

        for (int t = 0; t < 16; ++t) {
            if (t + 1 < 16) { load_wo(t + 1, (t + 1) & 1); CP_COMMIT(); CP_WAIT1(); }
            else            { CP_WAIT0(); }
            __syncthreads();

            const uint32_t sb = sbase + WO_OFF + (t & 1) * 16384;
            float acc[2][4][4];
#pragma unroll
            for (int a = 0; a < 2; ++a)
#pragma unroll
                for (int b = 0; b < 4; ++b)
#pragma unroll
                    for (int d = 0; d < 4; ++d) acc[a][b][d] = 0.f;

#pragma unroll
            for (int ks = 0; ks < 4; ++ks) {
                const int chunk = ks * 2 + ksel;
                uint32_t b[2][4];
#pragma unroll
                for (int p = 0; p < 2; ++p) {
                    const int r = warp_n * 32 + p * 16 + rl16;
                    LDMATRIX_X4(b[p], sb + r * 128 + ((chunk ^ (r & 7)) << 4));
                }
#pragma unroll
                for (int mt = 0; mt < 2; ++mt)
#pragma unroll
                    for (int nt = 0; nt < 4; ++nt)
                        mma_f16(acc[mt][nt], fa[mt][ks],
                                b[nt >> 1][nt & 1], b[nt >> 1][2 + (nt & 1)]);
            }

            const int nBase = t * 128 + warp_n * 32;
#pragma unroll
            for (int nt = 0; nt < 4; ++nt) {
                const int n = nBase + nt * 8 + tig * 2;
#pragma unroll
                for (int mt = 0; mt < 2; ++mt) {
                    int m = m0 + warp_m * 32 + mt * 16 + g;
                    float2 xv = *(const float2*)(x_t + (size_t)m * NH + n);
                    float2 o;
                    o.x = fmaf(gm, acc[mt][nt][0], xv.x);
                    o.y = fmaf(gm, acc[mt][nt][1], xv.y);
                    *(float2*)(y + (size_t)m * NH + n) = o;
                    m += 8;
                    xv = *(const float2*)(x_t + (size_t)m * NH + n);
                    o.x = fmaf(gm, acc[mt][nt][2], xv.x);
                    o.y = fmaf(gm, acc[mt][nt][3], xv.y);
                    *(float2*)(y + (size_t)m * NH + n) = o;
                }
            }
            __syncthreads();
        }
    }
}

// ---------------------------------------------------------------------------
extern "C" void kernel_launch(void* const* d_in, const int* in_sizes, int n_in,
                              void* d_out, int out_size)
{
    const float* h_prev    = (const float*)d_in[0];
    const float* x_t       = (const float*)d_in[1];
    const float* U_w       = (const float*)d_in[2];
    const float* U_b       = (const float*)d_in[3];
    const float* W_w       = (const float*)d_in[4];
    const float* alpha_raw = (const float*)d_in[5];
    const float* WQ        = (const float*)d_in[6];
    const float* WK        = (const float*)d_in[7];
    const float* WV        = (const float*)d_in[8];
    const float* WO        = (const float*)d_in[9];
    const float* gamma     = (const float*)d_in[10];

    float* h_t = (float*)d_out;
    float* y_t = h_t + (size_t)NB * NH;

    cudaFuncSetAttribute(k1_liquid_f16,
                         cudaFuncAttributeMaxDynamicSharedMemorySize, K1_SMEM);
    cudaFuncSetAttribute(k234_fused,
                         cudaFuncAttributeMaxDynamicSharedMemorySize, K234_SMEM);

    cvt_all<<<(CVT_TOTAL4 + 1023) / 1024, 256>>>(h_prev, x_t, W_w, U_w,
                                                 WQ, WK, WV, WO);

    dim3 g1(NH / 128, NB / 128);                      // 1024 CTAs
    k1_liquid_f16<<<g1, 256, K1_SMEM>>>(h_prev, U_b, alpha_raw, h_t);

    k234_fused<<<NB / 64, 256, K234_SMEM>>>(x_t, gamma, y_t);
}